// round 6
// baseline (speedup 1.0000x reference)
#include <cuda_runtime.h>
#include <cuda_bf16.h>
#include <math.h>

#define MAXN 50000
#define MAXE 800000

// ---------------- device scratch ----------------
__device__ __align__(16) float g_qkvs[(size_t)MAXN * 384]; // per node: q[128]|k[128]|v[128]
__device__ __align__(16) float g_agg [(size_t)MAXN * 128]; // normalized attention output
__device__ __align__(16) float g_W2  [64 * 64];            // Wskip @ Wc
__device__ float  g_b2[64];                                 // bskip @ Wc + bc
__device__ int    g_esrc [MAXE];
__device__ int    g_edst [MAXE];
__device__ int    g_src  [MAXE];
__device__ int    g_cnt  [MAXN];
__device__ int    g_cur  [MAXN];
__device__ int    g_rowptr[MAXN + 1];
__device__ int    g_blksum[64];
__device__ int    g_is64;
__device__ double g_stats[2];

// ---------------- init ----------------
__global__ void k_init(int n) {
    int i = blockIdx.x * blockDim.x + threadIdx.x;
    if (i < n) { g_cnt[i] = 0; g_cur[i] = 0; }
    if (i == 0) { g_stats[0] = 0.0; g_stats[1] = 0.0; }
}

// ---------------- edge dtype sniff ----------------
__global__ void k_detect(const void* __restrict__ ei) {
    if (threadIdx.x == 0 && blockIdx.x == 0) {
        const int* w = (const int*)ei;
        int all0 = 1;
        for (int i = 1; i < 64; i += 2) all0 &= (w[i] == 0);
        g_is64 = all0;
    }
}

// convert + fused dst histogram
__global__ void k_convert(const void* __restrict__ ei, int e) {
    int i = blockIdx.x * blockDim.x + threadIdx.x;
    if (i >= 2 * e) return;
    int v;
    if (g_is64) v = (int)((const long long*)ei)[i];
    else        v = ((const int*)ei)[i];
    if (i < e) g_esrc[i] = v;
    else { g_edst[i - e] = v; atomicAdd(&g_cnt[v], 1); }
}

// ---------------- QKV projection: [n,64]@[64,128] x3 ----------------
// BM=64, BN=128, block=256 (tx=0..31 -> 4 cols, ty=0..7 -> 8 rows), TM=8, TN=4.
// Xs k-major padded [32][68]: A-operand loads are warp-broadcast LDS.128.
__global__ void __launch_bounds__(256) k_gemm3(
        const float* __restrict__ x,
        const float* __restrict__ Wq, const float* __restrict__ bq,
        const float* __restrict__ Wk, const float* __restrict__ bk,
        const float* __restrict__ Wv, const float* __restrict__ bv,
        int n) {
    __shared__ float Xs[32][68];    // [k][row], padded (68) to kill STS conflicts
    __shared__ float Ws[32][128];   // [k][col]
    int m = blockIdx.y;
    const float* W    = (m == 0) ? Wq : (m == 1) ? Wk : Wv;
    const float* bias = (m == 0) ? bq : (m == 1) ? bk : bv;

    int tx = threadIdx.x & 31;      // 4 cols each
    int ty = threadIdx.x >> 5;      // 8 rows each (== warp id: A loads broadcast)
    int row0 = blockIdx.x * 64;

    float acc[8][4];
#pragma unroll
    for (int i = 0; i < 8; i++)
#pragma unroll
        for (int j = 0; j < 4; j++) acc[i][j] = 0.f;

    for (int kc = 0; kc < 2; kc++) {
        // X tile: 64 rows x 32 k -> k-major. 512 float4, 2 iters.
#pragma unroll
        for (int it = 0; it < 2; it++) {
            int idx = threadIdx.x + it * 256;   // 0..511
            int r = idx >> 3, kq = idx & 7;
            float4 xv = make_float4(0.f, 0.f, 0.f, 0.f);
            if (row0 + r < n) xv = ((const float4*)x)[(size_t)(row0 + r) * 16 + kc * 8 + kq];
            Xs[kq * 4 + 0][r] = xv.x;
            Xs[kq * 4 + 1][r] = xv.y;
            Xs[kq * 4 + 2][r] = xv.z;
            Xs[kq * 4 + 3][r] = xv.w;
        }
        // W tile: 32 k x 128 cols. 1024 float4, 4 iters.
#pragma unroll
        for (int it = 0; it < 4; it++) {
            int idx = threadIdx.x + it * 256;
            ((float4*)Ws)[idx] = ((const float4*)W)[kc * 1024 + idx];
        }
        __syncthreads();
#pragma unroll
        for (int k = 0; k < 32; k++) {
            float4 a0 = *(const float4*)&Xs[k][ty * 8];       // broadcast within warp
            float4 a1 = *(const float4*)&Xs[k][ty * 8 + 4];   // broadcast within warp
            float4 b  = *(const float4*)&Ws[k][tx * 4];       // coalesced
            float af[8] = {a0.x, a0.y, a0.z, a0.w, a1.x, a1.y, a1.z, a1.w};
#pragma unroll
            for (int i = 0; i < 8; i++) {
                acc[i][0] = fmaf(af[i], b.x, acc[i][0]);
                acc[i][1] = fmaf(af[i], b.y, acc[i][1]);
                acc[i][2] = fmaf(af[i], b.z, acc[i][2]);
                acc[i][3] = fmaf(af[i], b.w, acc[i][3]);
            }
        }
        __syncthreads();
    }
    // epilogue: bias + vector store
    float4 bv4 = *(const float4*)&bias[tx * 4];
#pragma unroll
    for (int i = 0; i < 8; i++) {
        int r = row0 + ty * 8 + i;
        if (r < n) {
            float4 o = make_float4(acc[i][0] + bv4.x, acc[i][1] + bv4.y,
                                   acc[i][2] + bv4.z, acc[i][3] + bv4.w);
            *(float4*)&g_qkvs[(size_t)r * 384 + m * 128 + tx * 4] = o;
        }
    }
}

// ---------------- W2 = Wskip @ Wc, b2 = bskip @ Wc + bc ----------------
__global__ void k_w2(const float* __restrict__ Wsk, const float* __restrict__ bsk,
                     const float* __restrict__ Wc, const float* __restrict__ bc) {
    int o = blockIdx.x * 256 + threadIdx.x;
    if (o < 64 * 64) {
        int r = o >> 6, c = o & 63;
        float s = 0.f;
#pragma unroll 8
        for (int k = 0; k < 128; k++) s = fmaf(Wsk[r * 128 + k], Wc[k * 64 + c], s);
        g_W2[o] = s;
    }
    if (blockIdx.x == 0 && threadIdx.x < 64) {
        int c = threadIdx.x;
        float s = bc[c];
#pragma unroll 8
        for (int k = 0; k < 128; k++) s = fmaf(bsk[k], Wc[k * 64 + c], s);
        g_b2[c] = s;
    }
}

// ---------------- CSR scan ----------------
__global__ void k_scan1(int n) {
    __shared__ int sh[1024];
    int tid = threadIdx.x;
    int i = blockIdx.x * 1024 + tid;
    int v = (i < n) ? g_cnt[i] : 0;
    sh[tid] = v;
    __syncthreads();
    for (int off = 1; off < 1024; off <<= 1) {
        int t = (tid >= off) ? sh[tid - off] : 0;
        __syncthreads();
        sh[tid] += t;
        __syncthreads();
    }
    if (i < n) g_rowptr[i] = sh[tid] - v;
    if (tid == 1023) g_blksum[blockIdx.x] = sh[1023];
}

__global__ void k_scan2(int nb, int n) {
    if (threadIdx.x == 0 && blockIdx.x == 0) {
        int acc = 0;
        for (int b = 0; b < nb; b++) { int t = g_blksum[b]; g_blksum[b] = acc; acc += t; }
        g_rowptr[n] = acc;
    }
}

__global__ void k_scan3(int n) {
    int i = blockIdx.x * 1024 + threadIdx.x;
    if (i < n) g_rowptr[i] += g_blksum[blockIdx.x];
}

__global__ void k_scatter(int e) {
    int i = blockIdx.x * blockDim.x + threadIdx.x;
    if (i < e) {
        int dst = g_edst[i];
        int pos = g_rowptr[dst] + atomicAdd(&g_cur[dst], 1);
        g_src[pos] = g_esrc[i];
    }
}

// ---------------- fused single-pass attention, unrolled x4: one warp per dst ----------------
__device__ __forceinline__ float warp16_dot(float4 q, float4 k) {
    float p = q.x * k.x + q.y * k.y + q.z * k.z + q.w * k.w;
    return p;
}

__global__ void k_attn(int n) {
    int node = blockIdx.x * 8 + (threadIdx.x >> 5);
    if (node >= n) return;
    int lane = threadIdx.x & 31;
    const float4* base = (const float4*)g_qkvs;   // stride 96 float4 per node

    float4 q4 = base[(size_t)node * 96 + lane];
    int beg = g_rowptr[node], end = g_rowptr[node + 1];

    float denom = 0.f;
    float4 acc = make_float4(0.f, 0.f, 0.f, 0.f);

    int t = beg;
    // main loop: 4 edges per iteration -> 8 independent LDG.128 in flight,
    // 4 interleaved (pipelined) shuffle-reduction chains
    for (; t + 4 <= end; t += 4) {
        int s0 = g_src[t + 0];
        int s1 = g_src[t + 1];
        int s2 = g_src[t + 2];
        int s3 = g_src[t + 3];
        const float4* p0 = base + (size_t)s0 * 96;
        const float4* p1 = base + (size_t)s1 * 96;
        const float4* p2 = base + (size_t)s2 * 96;
        const float4* p3 = base + (size_t)s3 * 96;
        float4 k0 = p0[32 + lane], v0 = p0[64 + lane];
        float4 k1 = p1[32 + lane], v1 = p1[64 + lane];
        float4 k2 = p2[32 + lane], v2 = p2[64 + lane];
        float4 k3 = p3[32 + lane], v3 = p3[64 + lane];

        float d0 = warp16_dot(q4, k0);
        float d1 = warp16_dot(q4, k1);
        float d2 = warp16_dot(q4, k2);
        float d3 = warp16_dot(q4, k3);
#pragma unroll
        for (int off = 8; off > 0; off >>= 1) {
            d0 += __shfl_xor_sync(0xffffffffu, d0, off);
            d1 += __shfl_xor_sync(0xffffffffu, d1, off);
            d2 += __shfl_xor_sync(0xffffffffu, d2, off);
            d3 += __shfl_xor_sync(0xffffffffu, d3, off);
        }
        float w0 = __expf(d0 * 0.125f);
        float w1 = __expf(d1 * 0.125f);
        float w2 = __expf(d2 * 0.125f);
        float w3 = __expf(d3 * 0.125f);
        denom += (w0 + w1) + (w2 + w3);
        acc.x = fmaf(w0, v0.x, fmaf(w1, v1.x, fmaf(w2, v2.x, fmaf(w3, v3.x, acc.x))));
        acc.y = fmaf(w0, v0.y, fmaf(w1, v1.y, fmaf(w2, v2.y, fmaf(w3, v3.y, acc.y))));
        acc.z = fmaf(w0, v0.z, fmaf(w1, v1.z, fmaf(w2, v2.z, fmaf(w3, v3.z, acc.z))));
        acc.w = fmaf(w0, v0.w, fmaf(w1, v1.w, fmaf(w2, v2.w, fmaf(w3, v3.w, acc.w))));
    }
    for (; t < end; t++) {
        int src = g_src[t];
        const float4* p = base + (size_t)src * 96;
        float4 k4 = p[32 + lane];
        float4 v4 = p[64 + lane];
        float pd = warp16_dot(q4, k4);
#pragma unroll
        for (int off = 8; off > 0; off >>= 1) pd += __shfl_xor_sync(0xffffffffu, pd, off);
        float w = __expf(pd * 0.125f);
        denom += w;
        acc.x = fmaf(w, v4.x, acc.x);
        acc.y = fmaf(w, v4.y, acc.y);
        acc.z = fmaf(w, v4.z, acc.z);
        acc.w = fmaf(w, v4.w, acc.w);
    }
    float inv = 1.f / (denom + 1e-16f);
    acc.x *= inv; acc.y *= inv; acc.z *= inv; acc.w *= inv;
    ((float4*)g_agg)[(size_t)node * 32 + lane] = acc;
}

// ---------------- final: out = agg@Wc + x@W2 + b2, fused LN stats ----------------
__global__ void k_final(const float* __restrict__ x, const float* __restrict__ Wc,
                        float* __restrict__ out, int n) {
    __shared__ float Ash[64 * 32];
    __shared__ float Wch[32 * 64];
    __shared__ float rs[8], rss[8];

    int tx = threadIdx.x & 15;
    int ty = threadIdx.x >> 4;
    int row0 = blockIdx.x * 64;

    float acc[4][4];
#pragma unroll
    for (int i = 0; i < 4; i++)
#pragma unroll
        for (int j = 0; j < 4; j++) acc[i][j] = 0.f;

    for (int kc = 0; kc < 6; kc++) {
        for (int t = threadIdx.x; t < 512; t += 256) {
            int r = t >> 3, q = t & 7;
            float4 av = make_float4(0.f, 0.f, 0.f, 0.f);
            if (row0 + r < n) {
                if (kc < 4) av = ((const float4*)g_agg)[(size_t)(row0 + r) * 32 + kc * 8 + q];
                else        av = ((const float4*)x)[(size_t)(row0 + r) * 16 + (kc - 4) * 8 + q];
            }
            ((float4*)Ash)[r * 8 + q] = av;
        }
        for (int t = threadIdx.x; t < 512; t += 256) {
            int k = t >> 4, c4 = t & 15;
            float4 wv;
            if (kc < 4) wv = ((const float4*)Wc)[(kc * 32 + k) * 16 + c4];
            else        wv = ((const float4*)g_W2)[((kc - 4) * 32 + k) * 16 + c4];
            ((float4*)Wch)[k * 16 + c4] = wv;
        }
        __syncthreads();
#pragma unroll
        for (int k = 0; k < 32; k++) {
            float xf[4], wf[4];
#pragma unroll
            for (int i = 0; i < 4; i++) xf[i] = Ash[(ty + i * 16) * 32 + k];
#pragma unroll
            for (int j = 0; j < 4; j++) wf[j] = Wch[k * 64 + tx + j * 16];
#pragma unroll
            for (int i = 0; i < 4; i++)
#pragma unroll
                for (int j = 0; j < 4; j++) acc[i][j] = fmaf(xf[i], wf[j], acc[i][j]);
        }
        __syncthreads();
    }

    float s = 0.f, ss = 0.f;
#pragma unroll
    for (int i = 0; i < 4; i++) {
        int r = row0 + ty + i * 16;
        if (r < n) {
#pragma unroll
            for (int j = 0; j < 4; j++) {
                int c = tx + j * 16;
                float v = acc[i][j] + g_b2[c];
                out[(size_t)r * 64 + c] = v;
                s += v;
                ss += v * v;
            }
        }
    }
#pragma unroll
    for (int off = 16; off > 0; off >>= 1) {
        s  += __shfl_xor_sync(0xffffffffu, s, off);
        ss += __shfl_xor_sync(0xffffffffu, ss, off);
    }
    int wid = threadIdx.x >> 5, lane = threadIdx.x & 31;
    if (lane == 0) { rs[wid] = s; rss[wid] = ss; }
    __syncthreads();
    if (threadIdx.x == 0) {
        double S = 0.0, SS = 0.0;
        for (int w = 0; w < 8; w++) { S += (double)rs[w]; SS += (double)rss[w]; }
        atomicAdd(&g_stats[0], S);
        atomicAdd(&g_stats[1], SS);
    }
}

// ---------------- graph-level LayerNorm ----------------
__global__ void k_norm(float* __restrict__ out, const float* __restrict__ gamma,
                       const float* __restrict__ beta, int total) {
    int i = blockIdx.x * blockDim.x + threadIdx.x;
    if (i < total) {
        double M = (double)total;
        double mean = g_stats[0] / M;
        double var  = g_stats[1] / M - mean * mean;
        if (var < 0.0) var = 0.0;
        float stdv = (float)sqrt(var);
        float v = out[i];
        int d = i & 63;
        out[i] = (v - (float)mean) / (stdv + 1e-5f) * __ldg(&gamma[d]) + __ldg(&beta[d]);
    }
}

// ---------------- launch ----------------
extern "C" void kernel_launch(void* const* d_in, const int* in_sizes, int n_in,
                              void* d_out, int out_size) {
    const float* x    = (const float*)d_in[0];
    const void*  ei   = d_in[1];
    const float* Wq   = (const float*)d_in[2];
    const float* bq   = (const float*)d_in[3];
    const float* Wk   = (const float*)d_in[4];
    const float* bk   = (const float*)d_in[5];
    const float* Wv   = (const float*)d_in[6];
    const float* bv   = (const float*)d_in[7];
    const float* Wsk  = (const float*)d_in[8];
    const float* bsk  = (const float*)d_in[9];
    const float* Wc   = (const float*)d_in[10];
    const float* bc   = (const float*)d_in[11];
    const float* gam  = (const float*)d_in[12];
    const float* bet  = (const float*)d_in[13];
    float* out = (float*)d_out;

    int n = in_sizes[0] / 64;
    int e = in_sizes[1] / 2;

    k_init<<<(n + 255) / 256, 256>>>(n);
    k_detect<<<1, 32>>>(ei);
    k_convert<<<(2 * e + 255) / 256, 256>>>(ei, e);
    k_gemm3<<<dim3((n + 63) / 64, 3), 256>>>(x, Wq, bq, Wk, bk, Wv, bv, n);
    k_w2<<<16, 256>>>(Wsk, bsk, Wc, bc);
    int nb = (n + 1023) / 1024;
    k_scan1<<<nb, 1024>>>(n);
    k_scan2<<<1, 32>>>(nb, n);
    k_scan3<<<nb, 1024>>>(n);
    k_scatter<<<(e + 255) / 256, 256>>>(e);
    k_attn<<<(n + 7) / 8, 256>>>(n);
    k_final<<<(n + 63) / 64, 256>>>(x, Wc, out, n);
    k_norm<<<(n * 64 + 255) / 256, 256>>>(out, gam, bet, n * 64);
}

// round 7
// speedup vs baseline: 1.0050x; 1.0050x over previous
#include <cuda_runtime.h>
#include <cuda_bf16.h>
#include <math.h>

#define MAXN 50000
#define MAXE 800000

// ---------------- device scratch ----------------
__device__ __align__(16) float g_qkvs[(size_t)MAXN * 384]; // per node: q[128]|k[128]|v[128]
__device__ __align__(16) float g_agg [(size_t)MAXN * 128]; // normalized attention output
__device__ __align__(16) float g_W2  [64 * 64];            // Wskip @ Wc
__device__ float  g_b2[64];                                 // bskip @ Wc + bc
__device__ int    g_esrc [MAXE];
__device__ int    g_edst [MAXE];
__device__ int    g_src  [MAXE];
__device__ int    g_cnt  [MAXN];
__device__ int    g_cur  [MAXN];
__device__ int    g_rowptr[MAXN + 1];
__device__ int    g_blksum[64];
__device__ int    g_is64;
__device__ double g_stats[2];

// ---------------- init ----------------
__global__ void k_init(int n) {
    int i = blockIdx.x * blockDim.x + threadIdx.x;
    if (i < n) { g_cnt[i] = 0; g_cur[i] = 0; }
    if (i == 0) { g_stats[0] = 0.0; g_stats[1] = 0.0; }
}

// ---------------- edge dtype sniff ----------------
__global__ void k_detect(const void* __restrict__ ei) {
    if (threadIdx.x == 0 && blockIdx.x == 0) {
        const int* w = (const int*)ei;
        int all0 = 1;
        for (int i = 1; i < 64; i += 2) all0 &= (w[i] == 0);
        g_is64 = all0;
    }
}

// convert + fused dst histogram
__global__ void k_convert(const void* __restrict__ ei, int e) {
    int i = blockIdx.x * blockDim.x + threadIdx.x;
    if (i >= 2 * e) return;
    int v;
    if (g_is64) v = (int)((const long long*)ei)[i];
    else        v = ((const int*)ei)[i];
    if (i < e) g_esrc[i] = v;
    else { g_edst[i - e] = v; atomicAdd(&g_cnt[v], 1); }
}

// ---------------- QKV projection: [n,64]@[64,128] x3 ----------------
// BM=64, BN=128, block=256 (tx=0..31 -> 4 cols, ty=0..7 -> 8 rows), TM=8, TN=4.
// Xs k-major padded [32][68]: A-operand loads are warp-broadcast LDS.128.
__global__ void __launch_bounds__(256) k_gemm3(
        const float* __restrict__ x,
        const float* __restrict__ Wq, const float* __restrict__ bq,
        const float* __restrict__ Wk, const float* __restrict__ bk,
        const float* __restrict__ Wv, const float* __restrict__ bv,
        int n) {
    __shared__ float Xs[32][68];    // [k][row], padded (68) to kill STS conflicts
    __shared__ float Ws[32][128];   // [k][col]
    int m = blockIdx.y;
    const float* W    = (m == 0) ? Wq : (m == 1) ? Wk : Wv;
    const float* bias = (m == 0) ? bq : (m == 1) ? bk : bv;

    int tx = threadIdx.x & 31;      // 4 cols each
    int ty = threadIdx.x >> 5;      // 8 rows each (== warp id: A loads broadcast)
    int row0 = blockIdx.x * 64;

    float acc[8][4];
#pragma unroll
    for (int i = 0; i < 8; i++)
#pragma unroll
        for (int j = 0; j < 4; j++) acc[i][j] = 0.f;

    for (int kc = 0; kc < 2; kc++) {
        // X tile: 64 rows x 32 k -> k-major. 512 float4, 2 iters.
#pragma unroll
        for (int it = 0; it < 2; it++) {
            int idx = threadIdx.x + it * 256;   // 0..511
            int r = idx >> 3, kq = idx & 7;
            float4 xv = make_float4(0.f, 0.f, 0.f, 0.f);
            if (row0 + r < n) xv = ((const float4*)x)[(size_t)(row0 + r) * 16 + kc * 8 + kq];
            Xs[kq * 4 + 0][r] = xv.x;
            Xs[kq * 4 + 1][r] = xv.y;
            Xs[kq * 4 + 2][r] = xv.z;
            Xs[kq * 4 + 3][r] = xv.w;
        }
        // W tile: 32 k x 128 cols. 1024 float4, 4 iters.
#pragma unroll
        for (int it = 0; it < 4; it++) {
            int idx = threadIdx.x + it * 256;
            ((float4*)Ws)[idx] = ((const float4*)W)[kc * 1024 + idx];
        }
        __syncthreads();
#pragma unroll
        for (int k = 0; k < 32; k++) {
            float4 a0 = *(const float4*)&Xs[k][ty * 8];       // broadcast within warp
            float4 a1 = *(const float4*)&Xs[k][ty * 8 + 4];   // broadcast within warp
            float4 b  = *(const float4*)&Ws[k][tx * 4];       // coalesced
            float af[8] = {a0.x, a0.y, a0.z, a0.w, a1.x, a1.y, a1.z, a1.w};
#pragma unroll
            for (int i = 0; i < 8; i++) {
                acc[i][0] = fmaf(af[i], b.x, acc[i][0]);
                acc[i][1] = fmaf(af[i], b.y, acc[i][1]);
                acc[i][2] = fmaf(af[i], b.z, acc[i][2]);
                acc[i][3] = fmaf(af[i], b.w, acc[i][3]);
            }
        }
        __syncthreads();
    }
    // epilogue: bias + vector store
    float4 bv4 = *(const float4*)&bias[tx * 4];
#pragma unroll
    for (int i = 0; i < 8; i++) {
        int r = row0 + ty * 8 + i;
        if (r < n) {
            float4 o = make_float4(acc[i][0] + bv4.x, acc[i][1] + bv4.y,
                                   acc[i][2] + bv4.z, acc[i][3] + bv4.w);
            *(float4*)&g_qkvs[(size_t)r * 384 + m * 128 + tx * 4] = o;
        }
    }
}

// ---------------- W2 = Wskip @ Wc, b2 = bskip @ Wc + bc ----------------
__global__ void k_w2(const float* __restrict__ Wsk, const float* __restrict__ bsk,
                     const float* __restrict__ Wc, const float* __restrict__ bc) {
    int o = blockIdx.x * 256 + threadIdx.x;
    if (o < 64 * 64) {
        int r = o >> 6, c = o & 63;
        float s = 0.f;
#pragma unroll 8
        for (int k = 0; k < 128; k++) s = fmaf(Wsk[r * 128 + k], Wc[k * 64 + c], s);
        g_W2[o] = s;
    }
    if (blockIdx.x == 0 && threadIdx.x < 64) {
        int c = threadIdx.x;
        float s = bc[c];
#pragma unroll 8
        for (int k = 0; k < 128; k++) s = fmaf(bsk[k], Wc[k * 64 + c], s);
        g_b2[c] = s;
    }
}

// ---------------- CSR scan ----------------
__global__ void k_scan1(int n) {
    __shared__ int sh[1024];
    int tid = threadIdx.x;
    int i = blockIdx.x * 1024 + tid;
    int v = (i < n) ? g_cnt[i] : 0;
    sh[tid] = v;
    __syncthreads();
    for (int off = 1; off < 1024; off <<= 1) {
        int t = (tid >= off) ? sh[tid - off] : 0;
        __syncthreads();
        sh[tid] += t;
        __syncthreads();
    }
    if (i < n) g_rowptr[i] = sh[tid] - v;
    if (tid == 1023) g_blksum[blockIdx.x] = sh[1023];
}

__global__ void k_scan2(int nb, int n) {
    if (threadIdx.x == 0 && blockIdx.x == 0) {
        int acc = 0;
        for (int b = 0; b < nb; b++) { int t = g_blksum[b]; g_blksum[b] = acc; acc += t; }
        g_rowptr[n] = acc;
    }
}

__global__ void k_scan3(int n) {
    int i = blockIdx.x * 1024 + threadIdx.x;
    if (i < n) g_rowptr[i] += g_blksum[blockIdx.x];
}

__global__ void k_scatter(int e) {
    int i = blockIdx.x * blockDim.x + threadIdx.x;
    if (i < e) {
        int dst = g_edst[i];
        int pos = g_rowptr[dst] + atomicAdd(&g_cur[dst], 1);
        g_src[pos] = g_esrc[i];
    }
}

// ---------------- fused single-pass attention, unrolled x4: one warp per dst ----------------
__device__ __forceinline__ float warp16_dot(float4 q, float4 k) {
    float p = q.x * k.x + q.y * k.y + q.z * k.z + q.w * k.w;
    return p;
}

__global__ void k_attn(int n) {
    int node = blockIdx.x * 8 + (threadIdx.x >> 5);
    if (node >= n) return;
    int lane = threadIdx.x & 31;
    const float4* base = (const float4*)g_qkvs;   // stride 96 float4 per node

    float4 q4 = base[(size_t)node * 96 + lane];
    int beg = g_rowptr[node], end = g_rowptr[node + 1];

    float denom = 0.f;
    float4 acc = make_float4(0.f, 0.f, 0.f, 0.f);

    int t = beg;
    // main loop: 4 edges per iteration -> 8 independent LDG.128 in flight,
    // 4 interleaved (pipelined) shuffle-reduction chains
    for (; t + 4 <= end; t += 4) {
        int s0 = g_src[t + 0];
        int s1 = g_src[t + 1];
        int s2 = g_src[t + 2];
        int s3 = g_src[t + 3];
        const float4* p0 = base + (size_t)s0 * 96;
        const float4* p1 = base + (size_t)s1 * 96;
        const float4* p2 = base + (size_t)s2 * 96;
        const float4* p3 = base + (size_t)s3 * 96;
        float4 k0 = p0[32 + lane], v0 = p0[64 + lane];
        float4 k1 = p1[32 + lane], v1 = p1[64 + lane];
        float4 k2 = p2[32 + lane], v2 = p2[64 + lane];
        float4 k3 = p3[32 + lane], v3 = p3[64 + lane];

        float d0 = warp16_dot(q4, k0);
        float d1 = warp16_dot(q4, k1);
        float d2 = warp16_dot(q4, k2);
        float d3 = warp16_dot(q4, k3);
#pragma unroll
        for (int off = 8; off > 0; off >>= 1) {
            d0 += __shfl_xor_sync(0xffffffffu, d0, off);
            d1 += __shfl_xor_sync(0xffffffffu, d1, off);
            d2 += __shfl_xor_sync(0xffffffffu, d2, off);
            d3 += __shfl_xor_sync(0xffffffffu, d3, off);
        }
        float w0 = __expf(d0 * 0.125f);
        float w1 = __expf(d1 * 0.125f);
        float w2 = __expf(d2 * 0.125f);
        float w3 = __expf(d3 * 0.125f);
        denom += (w0 + w1) + (w2 + w3);
        acc.x = fmaf(w0, v0.x, fmaf(w1, v1.x, fmaf(w2, v2.x, fmaf(w3, v3.x, acc.x))));
        acc.y = fmaf(w0, v0.y, fmaf(w1, v1.y, fmaf(w2, v2.y, fmaf(w3, v3.y, acc.y))));
        acc.z = fmaf(w0, v0.z, fmaf(w1, v1.z, fmaf(w2, v2.z, fmaf(w3, v3.z, acc.z))));
        acc.w = fmaf(w0, v0.w, fmaf(w1, v1.w, fmaf(w2, v2.w, fmaf(w3, v3.w, acc.w))));
    }
    for (; t < end; t++) {
        int src = g_src[t];
        const float4* p = base + (size_t)src * 96;
        float4 k4 = p[32 + lane];
        float4 v4 = p[64 + lane];
        float pd = warp16_dot(q4, k4);
#pragma unroll
        for (int off = 8; off > 0; off >>= 1) pd += __shfl_xor_sync(0xffffffffu, pd, off);
        float w = __expf(pd * 0.125f);
        denom += w;
        acc.x = fmaf(w, v4.x, acc.x);
        acc.y = fmaf(w, v4.y, acc.y);
        acc.z = fmaf(w, v4.z, acc.z);
        acc.w = fmaf(w, v4.w, acc.w);
    }
    float inv = 1.f / (denom + 1e-16f);
    acc.x *= inv; acc.y *= inv; acc.z *= inv; acc.w *= inv;
    ((float4*)g_agg)[(size_t)node * 32 + lane] = acc;
}

// ---------------- final: out = agg@Wc + x@W2 + b2, fused LN stats ----------------
__global__ void k_final(const float* __restrict__ x, const float* __restrict__ Wc,
                        float* __restrict__ out, int n) {
    __shared__ float Ash[64 * 32];
    __shared__ float Wch[32 * 64];
    __shared__ float rs[8], rss[8];

    int tx = threadIdx.x & 15;
    int ty = threadIdx.x >> 4;
    int row0 = blockIdx.x * 64;

    float acc[4][4];
#pragma unroll
    for (int i = 0; i < 4; i++)
#pragma unroll
        for (int j = 0; j < 4; j++) acc[i][j] = 0.f;

    for (int kc = 0; kc < 6; kc++) {
        for (int t = threadIdx.x; t < 512; t += 256) {
            int r = t >> 3, q = t & 7;
            float4 av = make_float4(0.f, 0.f, 0.f, 0.f);
            if (row0 + r < n) {
                if (kc < 4) av = ((const float4*)g_agg)[(size_t)(row0 + r) * 32 + kc * 8 + q];
                else        av = ((const float4*)x)[(size_t)(row0 + r) * 16 + (kc - 4) * 8 + q];
            }
            ((float4*)Ash)[r * 8 + q] = av;
        }
        for (int t = threadIdx.x; t < 512; t += 256) {
            int k = t >> 4, c4 = t & 15;
            float4 wv;
            if (kc < 4) wv = ((const float4*)Wc)[(kc * 32 + k) * 16 + c4];
            else        wv = ((const float4*)g_W2)[((kc - 4) * 32 + k) * 16 + c4];
            ((float4*)Wch)[k * 16 + c4] = wv;
        }
        __syncthreads();
#pragma unroll
        for (int k = 0; k < 32; k++) {
            float xf[4], wf[4];
#pragma unroll
            for (int i = 0; i < 4; i++) xf[i] = Ash[(ty + i * 16) * 32 + k];
#pragma unroll
            for (int j = 0; j < 4; j++) wf[j] = Wch[k * 64 + tx + j * 16];
#pragma unroll
            for (int i = 0; i < 4; i++)
#pragma unroll
                for (int j = 0; j < 4; j++) acc[i][j] = fmaf(xf[i], wf[j], acc[i][j]);
        }
        __syncthreads();
    }

    float s = 0.f, ss = 0.f;
#pragma unroll
    for (int i = 0; i < 4; i++) {
        int r = row0 + ty + i * 16;
        if (r < n) {
#pragma unroll
            for (int j = 0; j < 4; j++) {
                int c = tx + j * 16;
                float v = acc[i][j] + g_b2[c];
                out[(size_t)r * 64 + c] = v;
                s += v;
                ss += v * v;
            }
        }
    }
#pragma unroll
    for (int off = 16; off > 0; off >>= 1) {
        s  += __shfl_xor_sync(0xffffffffu, s, off);
        ss += __shfl_xor_sync(0xffffffffu, ss, off);
    }
    int wid = threadIdx.x >> 5, lane = threadIdx.x & 31;
    if (lane == 0) { rs[wid] = s; rss[wid] = ss; }
    __syncthreads();
    if (threadIdx.x == 0) {
        double S = 0.0, SS = 0.0;
        for (int w = 0; w < 8; w++) { S += (double)rs[w]; SS += (double)rss[w]; }
        atomicAdd(&g_stats[0], S);
        atomicAdd(&g_stats[1], SS);
    }
}

// ---------------- graph-level LayerNorm ----------------
__global__ void k_norm(float* __restrict__ out, const float* __restrict__ gamma,
                       const float* __restrict__ beta, int total) {
    int i = blockIdx.x * blockDim.x + threadIdx.x;
    if (i < total) {
        double M = (double)total;
        double mean = g_stats[0] / M;
        double var  = g_stats[1] / M - mean * mean;
        if (var < 0.0) var = 0.0;
        float stdv = (float)sqrt(var);
        float v = out[i];
        int d = i & 63;
        out[i] = (v - (float)mean) / (stdv + 1e-5f) * __ldg(&gamma[d]) + __ldg(&beta[d]);
    }
}

// ---------------- launch ----------------
extern "C" void kernel_launch(void* const* d_in, const int* in_sizes, int n_in,
                              void* d_out, int out_size) {
    const float* x    = (const float*)d_in[0];
    const void*  ei   = d_in[1];
    const float* Wq   = (const float*)d_in[2];
    const float* bq   = (const float*)d_in[3];
    const float* Wk   = (const float*)d_in[4];
    const float* bk   = (const float*)d_in[5];
    const float* Wv   = (const float*)d_in[6];
    const float* bv   = (const float*)d_in[7];
    const float* Wsk  = (const float*)d_in[8];
    const float* bsk  = (const float*)d_in[9];
    const float* Wc   = (const float*)d_in[10];
    const float* bc   = (const float*)d_in[11];
    const float* gam  = (const float*)d_in[12];
    const float* bet  = (const float*)d_in[13];
    float* out = (float*)d_out;

    int n = in_sizes[0] / 64;
    int e = in_sizes[1] / 2;

    k_init<<<(n + 255) / 256, 256>>>(n);
    k_detect<<<1, 32>>>(ei);
    k_convert<<<(2 * e + 255) / 256, 256>>>(ei, e);
    k_gemm3<<<dim3((n + 63) / 64, 3), 256>>>(x, Wq, bq, Wk, bk, Wv, bv, n);
    k_w2<<<16, 256>>>(Wsk, bsk, Wc, bc);
    int nb = (n + 1023) / 1024;
    k_scan1<<<nb, 1024>>>(n);
    k_scan2<<<1, 32>>>(nb, n);
    k_scan3<<<nb, 1024>>>(n);
    k_scatter<<<(e + 255) / 256, 256>>>(e);
    k_attn<<<(n + 7) / 8, 256>>>(n);
    k_final<<<(n + 63) / 64, 256>>>(x, Wc, out, n);
    k_norm<<<(n * 64 + 255) / 256, 256>>>(out, gam, bet, n * 64);
}

// round 8
// speedup vs baseline: 1.0931x; 1.0876x over previous
#include <cuda_runtime.h>
#include <cuda_bf16.h>
#include <math.h>

#define MAXN 50000
#define MAXE 800000

// ---------------- device scratch ----------------
__device__ __align__(16) float g_qt [(size_t)MAXN * 128];  // x @ (Wq Wk^T) per head
__device__ __align__(16) __nv_bfloat16 g_v[(size_t)MAXN * 128]; // projected v, bf16
__device__ __align__(16) float2 g_ec[MAXN];                 // exp(x·g_h/8) per head
__device__ __align__(16) float g_agg[(size_t)MAXN * 128];   // attention output
__device__ __align__(16) float g_M  [64 * 128];             // Mcat
__device__ __align__(16) float g_W2 [64 * 64];              // Wskip @ Wc
__device__ float  g_gvec[128];                               // Wk_h @ bq_h per head
__device__ float  g_b2[64];                                  // bskip@Wc + bc
__device__ int    g_esrc [MAXE];
__device__ int    g_edst [MAXE];
__device__ int    g_srcs [MAXE];
__device__ int    g_cnt  [MAXN];
__device__ int    g_cur  [MAXN];
__device__ int    g_rowptr[MAXN + 1];
__device__ int    g_blksum[64];
__device__ int    g_is64;
__device__ double g_stats[2];

// ---------------- init ----------------
__global__ void k_init(int n) {
    int i = blockIdx.x * blockDim.x + threadIdx.x;
    if (i < n) { g_cnt[i] = 0; g_cur[i] = 0; }
    if (i == 0) { g_stats[0] = 0.0; g_stats[1] = 0.0; }
}

// ---------------- edge dtype sniff ----------------
__global__ void k_detect(const void* __restrict__ ei) {
    if (threadIdx.x == 0 && blockIdx.x == 0) {
        const int* w = (const int*)ei;
        int all0 = 1;
        for (int i = 1; i < 64; i += 2) all0 &= (w[i] == 0);
        g_is64 = all0;
    }
}

// convert + fused dst histogram
__global__ void k_convert(const void* __restrict__ ei, int e) {
    int i = blockIdx.x * blockDim.x + threadIdx.x;
    if (i >= 2 * e) return;
    int v;
    if (g_is64) v = (int)((const long long*)ei)[i];
    else        v = ((const int*)ei)[i];
    if (i < e) g_esrc[i] = v;
    else { g_edst[i - e] = v; atomicAdd(&g_cnt[v], 1); }
}

// ---------------- tiny precomputes: Mcat, W2, b2, gvec ----------------
// Mcat[i][h*64+j] = sum_c Wq[i][h*64+c] * Wk[j][h*64+c]
// W2 = Wskip @ Wc ; b2 = bskip @ Wc + bc ; gvec[h*64+i] = sum_j Wk[i][h*64+j]*bq[h*64+j]
__global__ void k_prep(const float* __restrict__ Wq, const float* __restrict__ bq,
                       const float* __restrict__ Wk,
                       const float* __restrict__ Wsk, const float* __restrict__ bsk,
                       const float* __restrict__ Wc, const float* __restrict__ bc) {
    int idx = blockIdx.x * 256 + threadIdx.x;
    if (idx < 8192) {                  // Mcat
        int i = idx >> 7, col = idx & 127, h = col >> 6, j = col & 63;
        const float* wq = Wq + i * 128 + h * 64;
        const float* wk = Wk + j * 128 + h * 64;
        float s = 0.f;
#pragma unroll 8
        for (int c = 0; c < 64; c++) s = fmaf(wq[c], wk[c], s);
        g_M[idx] = s;
    } else if (idx < 12288) {          // W2
        int o = idx - 8192, r = o >> 6, c = o & 63;
        float s = 0.f;
#pragma unroll 8
        for (int k = 0; k < 128; k++) s = fmaf(Wsk[r * 128 + k], Wc[k * 64 + c], s);
        g_W2[o] = s;
    } else if (idx < 12352) {          // b2
        int c = idx - 12288;
        float s = bc[c];
#pragma unroll 8
        for (int k = 0; k < 128; k++) s = fmaf(bsk[k], Wc[k * 64 + c], s);
        g_b2[c] = s;
    } else if (idx < 12480) {          // gvec
        int o = idx - 12352, h = o >> 6, i = o & 63;
        float s = 0.f;
#pragma unroll 8
        for (int j = 0; j < 64; j++) s = fmaf(Wk[i * 128 + h * 64 + j], bq[h * 64 + j], s);
        g_gvec[o] = s;
    }
}

// ---------------- projections: qt = x@Mcat (fp32), v = x@Wv+bv (bf16) ----------------
// BM=64, BN=128, block=256, TM=8 TN=4, warp-broadcast A loads.
__global__ void __launch_bounds__(256) k_gemm2(
        const float* __restrict__ x,
        const float* __restrict__ Wv, const float* __restrict__ bv,
        int n) {
    __shared__ float Xs[32][68];
    __shared__ float Ws[32][128];
    int m = blockIdx.y;
    const float* W = (m == 0) ? (const float*)g_M : Wv;

    int tx = threadIdx.x & 31;
    int ty = threadIdx.x >> 5;
    int row0 = blockIdx.x * 64;

    float acc[8][4];
#pragma unroll
    for (int i = 0; i < 8; i++)
#pragma unroll
        for (int j = 0; j < 4; j++) acc[i][j] = 0.f;

    for (int kc = 0; kc < 2; kc++) {
#pragma unroll
        for (int it = 0; it < 2; it++) {
            int idx = threadIdx.x + it * 256;
            int r = idx >> 3, kq = idx & 7;
            float4 xv = make_float4(0.f, 0.f, 0.f, 0.f);
            if (row0 + r < n) xv = ((const float4*)x)[(size_t)(row0 + r) * 16 + kc * 8 + kq];
            Xs[kq * 4 + 0][r] = xv.x;
            Xs[kq * 4 + 1][r] = xv.y;
            Xs[kq * 4 + 2][r] = xv.z;
            Xs[kq * 4 + 3][r] = xv.w;
        }
#pragma unroll
        for (int it = 0; it < 4; it++) {
            int idx = threadIdx.x + it * 256;
            ((float4*)Ws)[idx] = ((const float4*)W)[kc * 1024 + idx];
        }
        __syncthreads();
#pragma unroll
        for (int k = 0; k < 32; k++) {
            float4 a0 = *(const float4*)&Xs[k][ty * 8];
            float4 a1 = *(const float4*)&Xs[k][ty * 8 + 4];
            float4 b  = *(const float4*)&Ws[k][tx * 4];
            float af[8] = {a0.x, a0.y, a0.z, a0.w, a1.x, a1.y, a1.z, a1.w};
#pragma unroll
            for (int i = 0; i < 8; i++) {
                acc[i][0] = fmaf(af[i], b.x, acc[i][0]);
                acc[i][1] = fmaf(af[i], b.y, acc[i][1]);
                acc[i][2] = fmaf(af[i], b.z, acc[i][2]);
                acc[i][3] = fmaf(af[i], b.w, acc[i][3]);
            }
        }
        __syncthreads();
    }
    if (m == 0) {                       // qt: fp32, no bias
#pragma unroll
        for (int i = 0; i < 8; i++) {
            int r = row0 + ty * 8 + i;
            if (r < n)
                *(float4*)&g_qt[(size_t)r * 128 + tx * 4] =
                    make_float4(acc[i][0], acc[i][1], acc[i][2], acc[i][3]);
        }
    } else {                            // v: bias + bf16 pack
        float4 bv4 = *(const float4*)&bv[tx * 4];
#pragma unroll
        for (int i = 0; i < 8; i++) {
            int r = row0 + ty * 8 + i;
            if (r < n) {
                __nv_bfloat162 lo = __floats2bfloat162_rn(acc[i][0] + bv4.x, acc[i][1] + bv4.y);
                __nv_bfloat162 hi = __floats2bfloat162_rn(acc[i][2] + bv4.z, acc[i][3] + bv4.w);
                uint2 u;
                u.x = *(unsigned*)&lo;
                u.y = *(unsigned*)&hi;
                *(uint2*)&g_v[(size_t)r * 128 + tx * 4] = u;
            }
        }
    }
}

// ---------------- per-node src factors: ec_h = exp(x·gvec_h / 8) ----------------
__global__ void k_ec(const float* __restrict__ x, int n) {
    __shared__ float4 gs[32];
    if (threadIdx.x < 32) gs[threadIdx.x] = ((const float4*)g_gvec)[threadIdx.x];
    __syncthreads();
    int node = blockIdx.x * 256 + threadIdx.x;
    if (node >= n) return;
    const float4* xr = (const float4*)(x + (size_t)node * 64);
    float a0 = 0.f, a1 = 0.f;
#pragma unroll
    for (int q = 0; q < 16; q++) {
        float4 xv = xr[q];
        float4 h0 = gs[q], h1 = gs[16 + q];
        a0 += xv.x * h0.x + xv.y * h0.y + xv.z * h0.z + xv.w * h0.w;
        a1 += xv.x * h1.x + xv.y * h1.y + xv.z * h1.z + xv.w * h1.w;
    }
    g_ec[node] = make_float2(__expf(a0 * 0.125f), __expf(a1 * 0.125f));
}

// ---------------- CSR scan ----------------
__global__ void k_scan1(int n) {
    __shared__ int sh[1024];
    int tid = threadIdx.x;
    int i = blockIdx.x * 1024 + tid;
    int v = (i < n) ? g_cnt[i] : 0;
    sh[tid] = v;
    __syncthreads();
    for (int off = 1; off < 1024; off <<= 1) {
        int t = (tid >= off) ? sh[tid - off] : 0;
        __syncthreads();
        sh[tid] += t;
        __syncthreads();
    }
    if (i < n) g_rowptr[i] = sh[tid] - v;
    if (tid == 1023) g_blksum[blockIdx.x] = sh[1023];
}

__global__ void k_scan2(int nb, int n) {
    if (threadIdx.x == 0 && blockIdx.x == 0) {
        int acc = 0;
        for (int b = 0; b < nb; b++) { int t = g_blksum[b]; g_blksum[b] = acc; acc += t; }
        g_rowptr[n] = acc;
    }
}

__global__ void k_scan3(int n) {
    int i = blockIdx.x * 1024 + threadIdx.x;
    if (i < n) g_rowptr[i] += g_blksum[blockIdx.x];
}

__global__ void k_scatter(int e) {
    int i = blockIdx.x * blockDim.x + threadIdx.x;
    if (i < e) {
        int dst = g_edst[i];
        int pos = g_rowptr[dst] + atomicAdd(&g_cur[dst], 1);
        g_srcs[pos] = g_esrc[i];
    }
}

// ---------------- attention: one warp per dst, gather x_s (256B) + v_s (bf16 256B) ----------------
// weight = exp(qt_d · x_s / 8) * ec_h(s); dst-side softmax factors cancel exactly.
__global__ void __launch_bounds__(256) k_attn(const float* __restrict__ x, int n) {
    int node = blockIdx.x * 8 + (threadIdx.x >> 5);
    if (node >= n) return;
    int lane = threadIdx.x & 31;
    int l15 = lane & 15;

    float4 qt = *(const float4*)&g_qt[(size_t)node * 128 + lane * 4];
    int beg = g_rowptr[node], end = g_rowptr[node + 1];

    float denom = 0.f;
    float4 acc = make_float4(0.f, 0.f, 0.f, 0.f);

    int t = beg;
    for (; t + 4 <= end; t += 4) {
        int s0 = g_srcs[t + 0], s1 = g_srcs[t + 1], s2 = g_srcs[t + 2], s3 = g_srcs[t + 3];
        float4 x0 = ((const float4*)x)[(size_t)s0 * 16 + l15];
        float4 x1 = ((const float4*)x)[(size_t)s1 * 16 + l15];
        float4 x2 = ((const float4*)x)[(size_t)s2 * 16 + l15];
        float4 x3 = ((const float4*)x)[(size_t)s3 * 16 + l15];
        uint2 u0 = *(const uint2*)&g_v[(size_t)s0 * 128 + lane * 4];
        uint2 u1 = *(const uint2*)&g_v[(size_t)s1 * 128 + lane * 4];
        uint2 u2 = *(const uint2*)&g_v[(size_t)s2 * 128 + lane * 4];
        uint2 u3 = *(const uint2*)&g_v[(size_t)s3 * 128 + lane * 4];
        float2 e0 = g_ec[s0], e1 = g_ec[s1], e2 = g_ec[s2], e3 = g_ec[s3];

        float d0 = qt.x * x0.x + qt.y * x0.y + qt.z * x0.z + qt.w * x0.w;
        float d1 = qt.x * x1.x + qt.y * x1.y + qt.z * x1.z + qt.w * x1.w;
        float d2 = qt.x * x2.x + qt.y * x2.y + qt.z * x2.z + qt.w * x2.w;
        float d3 = qt.x * x3.x + qt.y * x3.y + qt.z * x3.z + qt.w * x3.w;
#pragma unroll
        for (int off = 8; off > 0; off >>= 1) {
            d0 += __shfl_xor_sync(0xffffffffu, d0, off);
            d1 += __shfl_xor_sync(0xffffffffu, d1, off);
            d2 += __shfl_xor_sync(0xffffffffu, d2, off);
            d3 += __shfl_xor_sync(0xffffffffu, d3, off);
        }
        float w0 = __expf(d0 * 0.125f) * ((lane < 16) ? e0.x : e0.y);
        float w1 = __expf(d1 * 0.125f) * ((lane < 16) ? e1.x : e1.y);
        float w2 = __expf(d2 * 0.125f) * ((lane < 16) ? e2.x : e2.y);
        float w3 = __expf(d3 * 0.125f) * ((lane < 16) ? e3.x : e3.y);
        denom += (w0 + w1) + (w2 + w3);

        float2 a, b;
        a = __bfloat1622float2(*(__nv_bfloat162*)&u0.x);
        b = __bfloat1622float2(*(__nv_bfloat162*)&u0.y);
        acc.x = fmaf(w0, a.x, acc.x); acc.y = fmaf(w0, a.y, acc.y);
        acc.z = fmaf(w0, b.x, acc.z); acc.w = fmaf(w0, b.y, acc.w);
        a = __bfloat1622float2(*(__nv_bfloat162*)&u1.x);
        b = __bfloat1622float2(*(__nv_bfloat162*)&u1.y);
        acc.x = fmaf(w1, a.x, acc.x); acc.y = fmaf(w1, a.y, acc.y);
        acc.z = fmaf(w1, b.x, acc.z); acc.w = fmaf(w1, b.y, acc.w);
        a = __bfloat1622float2(*(__nv_bfloat162*)&u2.x);
        b = __bfloat1622float2(*(__nv_bfloat162*)&u2.y);
        acc.x = fmaf(w2, a.x, acc.x); acc.y = fmaf(w2, a.y, acc.y);
        acc.z = fmaf(w2, b.x, acc.z); acc.w = fmaf(w2, b.y, acc.w);
        a = __bfloat1622float2(*(__nv_bfloat162*)&u3.x);
        b = __bfloat1622float2(*(__nv_bfloat162*)&u3.y);
        acc.x = fmaf(w3, a.x, acc.x); acc.y = fmaf(w3, a.y, acc.y);
        acc.z = fmaf(w3, b.x, acc.z); acc.w = fmaf(w3, b.y, acc.w);
    }
    for (; t < end; t++) {
        int s = g_srcs[t];
        float4 xs = ((const float4*)x)[(size_t)s * 16 + l15];
        uint2 u = *(const uint2*)&g_v[(size_t)s * 128 + lane * 4];
        float2 e = g_ec[s];
        float d = qt.x * xs.x + qt.y * xs.y + qt.z * xs.z + qt.w * xs.w;
#pragma unroll
        for (int off = 8; off > 0; off >>= 1) d += __shfl_xor_sync(0xffffffffu, d, off);
        float w = __expf(d * 0.125f) * ((lane < 16) ? e.x : e.y);
        denom += w;
        float2 a = __bfloat1622float2(*(__nv_bfloat162*)&u.x);
        float2 b = __bfloat1622float2(*(__nv_bfloat162*)&u.y);
        acc.x = fmaf(w, a.x, acc.x); acc.y = fmaf(w, a.y, acc.y);
        acc.z = fmaf(w, b.x, acc.z); acc.w = fmaf(w, b.y, acc.w);
    }
    float inv = 1.f / (denom + 1e-16f);
    acc.x *= inv; acc.y *= inv; acc.z *= inv; acc.w *= inv;
    ((float4*)g_agg)[(size_t)node * 32 + lane] = acc;
}

// ---------------- final: out = agg@Wc + x@W2 + b2, fused LN stats ----------------
// BM=128, BN=64, block=256, TM=8 TN=4, half-warp-broadcast A loads.
__global__ void __launch_bounds__(256) k_final(const float* __restrict__ x,
                                               const float* __restrict__ Wc,
                                               float* __restrict__ out, int n) {
    __shared__ float Xs[32][132];
    __shared__ float Ws[32][64];
    __shared__ float rs[8], rss[8];

    int tx = threadIdx.x & 15;     // 4 cols
    int ty = threadIdx.x >> 4;     // 8 rows
    int row0 = blockIdx.x * 128;

    float acc[8][4];
#pragma unroll
    for (int i = 0; i < 8; i++)
#pragma unroll
        for (int j = 0; j < 4; j++) acc[i][j] = 0.f;

    for (int kc = 0; kc < 6; kc++) {
        // A tile: 128 rows x 32 k -> k-major
#pragma unroll
        for (int it = 0; it < 4; it++) {
            int idx = threadIdx.x + it * 256;   // 0..1023
            int r = idx >> 3, kq = idx & 7;
            float4 av = make_float4(0.f, 0.f, 0.f, 0.f);
            if (row0 + r < n) {
                if (kc < 4) av = ((const float4*)g_agg)[(size_t)(row0 + r) * 32 + kc * 8 + kq];
                else        av = ((const float4*)x)[(size_t)(row0 + r) * 16 + (kc - 4) * 8 + kq];
            }
            Xs[kq * 4 + 0][r] = av.x;
            Xs[kq * 4 + 1][r] = av.y;
            Xs[kq * 4 + 2][r] = av.z;
            Xs[kq * 4 + 3][r] = av.w;
        }
        // B tile: 32 k x 64 cols
#pragma unroll
        for (int it = 0; it < 2; it++) {
            int idx = threadIdx.x + it * 256;   // 0..511
            int k = idx >> 4, c4 = idx & 15;
            float4 wv;
            if (kc < 4) wv = ((const float4*)Wc)[(kc * 32 + k) * 16 + c4];
            else        wv = ((const float4*)g_W2)[((kc - 4) * 32 + k) * 16 + c4];
            *(float4*)&Ws[k][c4 * 4] = wv;
        }
        __syncthreads();
#pragma unroll
        for (int k = 0; k < 32; k++) {
            float4 a0 = *(const float4*)&Xs[k][ty * 8];
            float4 a1 = *(const float4*)&Xs[k][ty * 8 + 4];
            float4 b  = *(const float4*)&Ws[k][tx * 4];
            float af[8] = {a0.x, a0.y, a0.z, a0.w, a1.x, a1.y, a1.z, a1.w};
#pragma unroll
            for (int i = 0; i < 8; i++) {
                acc[i][0] = fmaf(af[i], b.x, acc[i][0]);
                acc[i][1] = fmaf(af[i], b.y, acc[i][1]);
                acc[i][2] = fmaf(af[i], b.z, acc[i][2]);
                acc[i][3] = fmaf(af[i], b.w, acc[i][3]);
            }
        }
        __syncthreads();
    }

    float4 b2 = *(const float4*)&g_b2[tx * 4];
    float s = 0.f, ss = 0.f;
#pragma unroll
    for (int i = 0; i < 8; i++) {
        int r = row0 + ty * 8 + i;
        if (r < n) {
            float4 o = make_float4(acc[i][0] + b2.x, acc[i][1] + b2.y,
                                   acc[i][2] + b2.z, acc[i][3] + b2.w);
            *(float4*)&out[(size_t)r * 64 + tx * 4] = o;
            s += (o.x + o.y) + (o.z + o.w);
            ss += o.x * o.x + o.y * o.y + o.z * o.z + o.w * o.w;
        }
    }
#pragma unroll
    for (int off = 16; off > 0; off >>= 1) {
        s  += __shfl_xor_sync(0xffffffffu, s, off);
        ss += __shfl_xor_sync(0xffffffffu, ss, off);
    }
    int wid = threadIdx.x >> 5, lane = threadIdx.x & 31;
    if (lane == 0) { rs[wid] = s; rss[wid] = ss; }
    __syncthreads();
    if (threadIdx.x == 0) {
        double S = 0.0, SS = 0.0;
        for (int w = 0; w < 8; w++) { S += (double)rs[w]; SS += (double)rss[w]; }
        atomicAdd(&g_stats[0], S);
        atomicAdd(&g_stats[1], SS);
    }
}

// ---------------- graph-level LayerNorm ----------------
__global__ void k_norm(float* __restrict__ out, const float* __restrict__ gamma,
                       const float* __restrict__ beta, int total) {
    int i = blockIdx.x * blockDim.x + threadIdx.x;
    if (i < total) {
        double M = (double)total;
        double mean = g_stats[0] / M;
        double var  = g_stats[1] / M - mean * mean;
        if (var < 0.0) var = 0.0;
        float stdv = (float)sqrt(var);
        float v = out[i];
        int d = i & 63;
        out[i] = (v - (float)mean) / (stdv + 1e-5f) * __ldg(&gamma[d]) + __ldg(&beta[d]);
    }
}

// ---------------- launch ----------------
extern "C" void kernel_launch(void* const* d_in, const int* in_sizes, int n_in,
                              void* d_out, int out_size) {
    const float* x    = (const float*)d_in[0];
    const void*  ei   = d_in[1];
    const float* Wq   = (const float*)d_in[2];
    const float* bq   = (const float*)d_in[3];
    const float* Wk   = (const float*)d_in[4];
    const float* Wv   = (const float*)d_in[6];
    const float* bv   = (const float*)d_in[7];
    const float* Wsk  = (const float*)d_in[8];
    const float* bsk  = (const float*)d_in[9];
    const float* Wc   = (const float*)d_in[10];
    const float* bc   = (const float*)d_in[11];
    const float* gam  = (const float*)d_in[12];
    const float* bet  = (const float*)d_in[13];
    float* out = (float*)d_out;

    int n = in_sizes[0] / 64;
    int e = in_sizes[1] / 2;

    k_init<<<(n + 255) / 256, 256>>>(n);
    k_detect<<<1, 32>>>(ei);
    k_convert<<<(2 * e + 255) / 256, 256>>>(ei, e);
    k_prep<<<49, 256>>>(Wq, bq, Wk, Wsk, bsk, Wc, bc);
    k_gemm2<<<dim3((n + 63) / 64, 2), 256>>>(x, Wv, bv, n);
    k_ec<<<(n + 255) / 256, 256>>>(x, n);
    int nb = (n + 1023) / 1024;
    k_scan1<<<nb, 1024>>>(n);
    k_scan2<<<1, 32>>>(nb, n);
    k_scan3<<<nb, 1024>>>(n);
    k_scatter<<<(e + 255) / 256, 256>>>(e);
    k_attn<<<(n + 7) / 8, 256>>>(x, n);
    k_final<<<(n + 127) / 128, 256>>>(x, Wc, out, n);
    k_norm<<<(n * 64 + 255) / 256, 256>>>(out, gam, bet, n * 64);
}

// round 9
// speedup vs baseline: 1.1424x; 1.0451x over previous
#include <cuda_runtime.h>
#include <cuda_bf16.h>
#include <math.h>

#define MAXN 50000
#define MAXE 800000

// ---------------- device scratch ----------------
__device__ __align__(16) float g_qt [(size_t)MAXN * 128];       // x@(WqWk^T) + gvec
__device__ __align__(16) __nv_bfloat16 g_xb[(size_t)MAXN * 64]; // x in bf16 (gather side)
__device__ __align__(16) __nv_bfloat16 g_v [(size_t)MAXN * 128];// projected v, bf16
__device__ __align__(16) float g_agg[(size_t)MAXN * 128];       // attention output
__device__ __align__(16) float g_M  [64 * 128];                 // Mcat = Wq Wk^T per head
__device__ __align__(16) float g_W2 [64 * 64];                  // Wskip @ Wc
__device__ float  g_gvec[128];                                   // Wk_h @ bq_h per head
__device__ float  g_b2[64];                                      // bskip@Wc + bc
__device__ int    g_esrc [MAXE];
__device__ int    g_edst [MAXE];
__device__ int    g_srcs [MAXE];
__device__ int    g_cnt  [MAXN];
__device__ int    g_cur  [MAXN];
__device__ int    g_rowptr[MAXN + 1];
__device__ int    g_blksum[64];
__device__ int    g_is64;
__device__ double g_stats[2];

// ---------------- init ----------------
__global__ void k_init(int n) {
    int i = blockIdx.x * blockDim.x + threadIdx.x;
    if (i < n) { g_cnt[i] = 0; g_cur[i] = 0; }
    if (i == 0) { g_stats[0] = 0.0; g_stats[1] = 0.0; }
}

// ---------------- edge dtype sniff ----------------
__global__ void k_detect(const void* __restrict__ ei) {
    if (threadIdx.x == 0 && blockIdx.x == 0) {
        const int* w = (const int*)ei;
        int all0 = 1;
        for (int i = 1; i < 64; i += 2) all0 &= (w[i] == 0);
        g_is64 = all0;
    }
}

// convert + fused dst histogram
__global__ void k_convert(const void* __restrict__ ei, int e) {
    int i = blockIdx.x * blockDim.x + threadIdx.x;
    if (i >= 2 * e) return;
    int v;
    if (g_is64) v = (int)((const long long*)ei)[i];
    else        v = ((const int*)ei)[i];
    if (i < e) g_esrc[i] = v;
    else { g_edst[i - e] = v; atomicAdd(&g_cnt[v], 1); }
}

// ---------------- precomputes, 4 threads/output + quad shuffle reduce ----------------
// Mcat[i][h*64+j]=sum_c Wq[i][h64+c]Wk[j][h64+c]; W2=Wskip@Wc; b2=bskip@Wc+bc;
// gvec[h*64+i]=sum_j Wk[i][h64+j]*bq[h64+j]
__global__ void k_prep(const float* __restrict__ Wq, const float* __restrict__ bq,
                       const float* __restrict__ Wk,
                       const float* __restrict__ Wsk, const float* __restrict__ bsk,
                       const float* __restrict__ Wc, const float* __restrict__ bc) {
    int idx = blockIdx.x * 256 + threadIdx.x;
    int g = idx >> 2, part = idx & 3;
    float s = 0.f;
    int valid = 0;
    float* dst = 0;
    if (g < 8192) {                      // Mcat
        int i = g >> 7, col = g & 127, h = col >> 6, j = col & 63;
        const float* wq = Wq + i * 128 + h * 64 + part * 16;
        const float* wk = Wk + j * 128 + h * 64 + part * 16;
#pragma unroll
        for (int c = 0; c < 16; c++) s = fmaf(wq[c], wk[c], s);
        dst = &g_M[g]; valid = 1;
    } else if (g < 12288) {              // W2
        int o = g - 8192, r = o >> 6, c = o & 63;
#pragma unroll
        for (int k = 0; k < 32; k++)
            s = fmaf(Wsk[r * 128 + part * 32 + k], Wc[(part * 32 + k) * 64 + c], s);
        dst = &g_W2[o]; valid = 1;
    } else if (g < 12352) {              // b2
        int c = g - 12288;
        if (part == 0) s = bc[c];
#pragma unroll
        for (int k = 0; k < 32; k++) s = fmaf(bsk[part * 32 + k], Wc[(part * 32 + k) * 64 + c], s);
        dst = &g_b2[c]; valid = 1;
    } else if (g < 12480) {              // gvec
        int o = g - 12352, h = o >> 6, i = o & 63;
#pragma unroll
        for (int j = 0; j < 16; j++)
            s = fmaf(Wk[i * 128 + h * 64 + part * 16 + j], bq[h * 64 + part * 16 + j], s);
        dst = &g_gvec[o]; valid = 1;
    }
    s += __shfl_xor_sync(0xffffffffu, s, 1);
    s += __shfl_xor_sync(0xffffffffu, s, 2);
    if (valid && part == 0) *dst = s;
}

// ---------------- x -> bf16 copy (gather side of the attention dot) ----------------
__global__ void k_xb(const float* __restrict__ x, int n) {
    int i = blockIdx.x * 256 + threadIdx.x;   // one float4 (4 dims) per thread
    if (i < n * 16) {
        float4 xv = ((const float4*)x)[i];
        __nv_bfloat162 lo = __floats2bfloat162_rn(xv.x, xv.y);
        __nv_bfloat162 hi = __floats2bfloat162_rn(xv.z, xv.w);
        uint2 u;
        u.x = *(unsigned*)&lo;
        u.y = *(unsigned*)&hi;
        ((uint2*)g_xb)[i] = u;
    }
}

// ---------------- projections: qt = x@Mcat + gvec (fp32), v = x@Wv+bv (bf16) ----------------
__global__ void __launch_bounds__(256) k_gemm2(
        const float* __restrict__ x,
        const float* __restrict__ Wv, const float* __restrict__ bv,
        int n) {
    __shared__ float Xs[32][68];
    __shared__ float Ws[32][128];
    int m = blockIdx.y;
    const float* W    = (m == 0) ? (const float*)g_M : Wv;
    const float* bias = (m == 0) ? (const float*)g_gvec : bv;

    int tx = threadIdx.x & 31;
    int ty = threadIdx.x >> 5;
    int row0 = blockIdx.x * 64;

    float acc[8][4];
#pragma unroll
    for (int i = 0; i < 8; i++)
#pragma unroll
        for (int j = 0; j < 4; j++) acc[i][j] = 0.f;

    for (int kc = 0; kc < 2; kc++) {
#pragma unroll
        for (int it = 0; it < 2; it++) {
            int idx = threadIdx.x + it * 256;
            int r = idx >> 3, kq = idx & 7;
            float4 xv = make_float4(0.f, 0.f, 0.f, 0.f);
            if (row0 + r < n) xv = ((const float4*)x)[(size_t)(row0 + r) * 16 + kc * 8 + kq];
            Xs[kq * 4 + 0][r] = xv.x;
            Xs[kq * 4 + 1][r] = xv.y;
            Xs[kq * 4 + 2][r] = xv.z;
            Xs[kq * 4 + 3][r] = xv.w;
        }
#pragma unroll
        for (int it = 0; it < 4; it++) {
            int idx = threadIdx.x + it * 256;
            ((float4*)Ws)[idx] = ((const float4*)W)[kc * 1024 + idx];
        }
        __syncthreads();
#pragma unroll
        for (int k = 0; k < 32; k++) {
            float4 a0 = *(const float4*)&Xs[k][ty * 8];
            float4 a1 = *(const float4*)&Xs[k][ty * 8 + 4];
            float4 b  = *(const float4*)&Ws[k][tx * 4];
            float af[8] = {a0.x, a0.y, a0.z, a0.w, a1.x, a1.y, a1.z, a1.w};
#pragma unroll
            for (int i = 0; i < 8; i++) {
                acc[i][0] = fmaf(af[i], b.x, acc[i][0]);
                acc[i][1] = fmaf(af[i], b.y, acc[i][1]);
                acc[i][2] = fmaf(af[i], b.z, acc[i][2]);
                acc[i][3] = fmaf(af[i], b.w, acc[i][3]);
            }
        }
        __syncthreads();
    }
    float4 bv4 = *(const float4*)&bias[tx * 4];
    if (m == 0) {                       // qt' = x@Mcat + gvec (fp32)
#pragma unroll
        for (int i = 0; i < 8; i++) {
            int r = row0 + ty * 8 + i;
            if (r < n)
                *(float4*)&g_qt[(size_t)r * 128 + tx * 4] =
                    make_float4(acc[i][0] + bv4.x, acc[i][1] + bv4.y,
                                acc[i][2] + bv4.z, acc[i][3] + bv4.w);
        }
    } else {                            // v: bias + bf16 pack
#pragma unroll
        for (int i = 0; i < 8; i++) {
            int r = row0 + ty * 8 + i;
            if (r < n) {
                __nv_bfloat162 lo = __floats2bfloat162_rn(acc[i][0] + bv4.x, acc[i][1] + bv4.y);
                __nv_bfloat162 hi = __floats2bfloat162_rn(acc[i][2] + bv4.z, acc[i][3] + bv4.w);
                uint2 u;
                u.x = *(unsigned*)&lo;
                u.y = *(unsigned*)&hi;
                *(uint2*)&g_v[(size_t)r * 128 + tx * 4] = u;
            }
        }
    }
}

// ---------------- CSR scan ----------------
__global__ void k_scan1(int n) {
    __shared__ int sh[1024];
    int tid = threadIdx.x;
    int i = blockIdx.x * 1024 + tid;
    int v = (i < n) ? g_cnt[i] : 0;
    sh[tid] = v;
    __syncthreads();
    for (int off = 1; off < 1024; off <<= 1) {
        int t = (tid >= off) ? sh[tid - off] : 0;
        __syncthreads();
        sh[tid] += t;
        __syncthreads();
    }
    if (i < n) g_rowptr[i] = sh[tid] - v;
    if (tid == 1023) g_blksum[blockIdx.x] = sh[1023];
}

__global__ void k_scan2(int nb, int n) {
    if (threadIdx.x == 0 && blockIdx.x == 0) {
        int acc = 0;
        for (int b = 0; b < nb; b++) { int t = g_blksum[b]; g_blksum[b] = acc; acc += t; }
        g_rowptr[n] = acc;
    }
}

__global__ void k_scan3(int n) {
    int i = blockIdx.x * 1024 + threadIdx.x;
    if (i < n) g_rowptr[i] += g_blksum[blockIdx.x];
}

__global__ void k_scatter(int e) {
    int i = blockIdx.x * blockDim.x + threadIdx.x;
    if (i < e) {
        int dst = g_edst[i];
        int pos = g_rowptr[dst] + atomicAdd(&g_cur[dst], 1);
        g_srcs[pos] = g_esrc[i];
    }
}

// ---------------- attention: one warp per dst; gather xb (bf16 128B) + v (bf16 256B) ----------------
// weight = exp((qt_d + gvec) · x_s / 8); all dst-side softmax factors cancel exactly.
__global__ void __launch_bounds__(256) k_attn(int n) {
    int node = blockIdx.x * 8 + (threadIdx.x >> 5);
    if (node >= n) return;
    int lane = threadIdx.x & 31;
    int l15 = lane & 15;

    float4 qt = *(const float4*)&g_qt[(size_t)node * 128 + lane * 4];
    int beg = g_rowptr[node], end = g_rowptr[node + 1];

    const uint2* xb = (const uint2*)g_xb;   // 16 uint2 per node (64 bf16)
    const uint2* vb = (const uint2*)g_v;    // 32 uint2 per node (128 bf16)

    float denom = 0.f;
    float4 acc = make_float4(0.f, 0.f, 0.f, 0.f);

    int t = beg;
    for (; t + 4 <= end; t += 4) {
        int s0 = g_srcs[t + 0], s1 = g_srcs[t + 1], s2 = g_srcs[t + 2], s3 = g_srcs[t + 3];
        uint2 X0 = xb[(size_t)s0 * 16 + l15];
        uint2 X1 = xb[(size_t)s1 * 16 + l15];
        uint2 X2 = xb[(size_t)s2 * 16 + l15];
        uint2 X3 = xb[(size_t)s3 * 16 + l15];
        uint2 V0 = vb[(size_t)s0 * 32 + lane];
        uint2 V1 = vb[(size_t)s1 * 32 + lane];
        uint2 V2 = vb[(size_t)s2 * 32 + lane];
        uint2 V3 = vb[(size_t)s3 * 32 + lane];

        float2 a, b;
        a = __bfloat1622float2(*(__nv_bfloat162*)&X0.x);
        b = __bfloat1622float2(*(__nv_bfloat162*)&X0.y);
        float d0 = qt.x * a.x + qt.y * a.y + qt.z * b.x + qt.w * b.y;
        a = __bfloat1622float2(*(__nv_bfloat162*)&X1.x);
        b = __bfloat1622float2(*(__nv_bfloat162*)&X1.y);
        float d1 = qt.x * a.x + qt.y * a.y + qt.z * b.x + qt.w * b.y;
        a = __bfloat1622float2(*(__nv_bfloat162*)&X2.x);
        b = __bfloat1622float2(*(__nv_bfloat162*)&X2.y);
        float d2 = qt.x * a.x + qt.y * a.y + qt.z * b.x + qt.w * b.y;
        a = __bfloat1622float2(*(__nv_bfloat162*)&X3.x);
        b = __bfloat1622float2(*(__nv_bfloat162*)&X3.y);
        float d3 = qt.x * a.x + qt.y * a.y + qt.z * b.x + qt.w * b.y;
#pragma unroll
        for (int off = 8; off > 0; off >>= 1) {
            d0 += __shfl_xor_sync(0xffffffffu, d0, off);
            d1 += __shfl_xor_sync(0xffffffffu, d1, off);
            d2 += __shfl_xor_sync(0xffffffffu, d2, off);
            d3 += __shfl_xor_sync(0xffffffffu, d3, off);
        }
        float w0 = __expf(d0 * 0.125f);
        float w1 = __expf(d1 * 0.125f);
        float w2 = __expf(d2 * 0.125f);
        float w3 = __expf(d3 * 0.125f);
        denom += (w0 + w1) + (w2 + w3);

        a = __bfloat1622float2(*(__nv_bfloat162*)&V0.x);
        b = __bfloat1622float2(*(__nv_bfloat162*)&V0.y);
        acc.x = fmaf(w0, a.x, acc.x); acc.y = fmaf(w0, a.y, acc.y);
        acc.z = fmaf(w0, b.x, acc.z); acc.w = fmaf(w0, b.y, acc.w);
        a = __bfloat1622float2(*(__nv_bfloat162*)&V1.x);
        b = __bfloat1622float2(*(__nv_bfloat162*)&V1.y);
        acc.x = fmaf(w1, a.x, acc.x); acc.y = fmaf(w1, a.y, acc.y);
        acc.z = fmaf(w1, b.x, acc.z); acc.w = fmaf(w1, b.y, acc.w);
        a = __bfloat1622float2(*(__nv_bfloat162*)&V2.x);
        b = __bfloat1622float2(*(__nv_bfloat162*)&V2.y);
        acc.x = fmaf(w2, a.x, acc.x); acc.y = fmaf(w2, a.y, acc.y);
        acc.z = fmaf(w2, b.x, acc.z); acc.w = fmaf(w2, b.y, acc.w);
        a = __bfloat1622float2(*(__nv_bfloat162*)&V3.x);
        b = __bfloat1622float2(*(__nv_bfloat162*)&V3.y);
        acc.x = fmaf(w3, a.x, acc.x); acc.y = fmaf(w3, a.y, acc.y);
        acc.z = fmaf(w3, b.x, acc.z); acc.w = fmaf(w3, b.y, acc.w);
    }
    for (; t < end; t++) {
        int s = g_srcs[t];
        uint2 X = xb[(size_t)s * 16 + l15];
        uint2 V = vb[(size_t)s * 32 + lane];
        float2 a = __bfloat1622float2(*(__nv_bfloat162*)&X.x);
        float2 b = __bfloat1622float2(*(__nv_bfloat162*)&X.y);
        float d = qt.x * a.x + qt.y * a.y + qt.z * b.x + qt.w * b.y;
#pragma unroll
        for (int off = 8; off > 0; off >>= 1) d += __shfl_xor_sync(0xffffffffu, d, off);
        float w = __expf(d * 0.125f);
        denom += w;
        a = __bfloat1622float2(*(__nv_bfloat162*)&V.x);
        b = __bfloat1622float2(*(__nv_bfloat162*)&V.y);
        acc.x = fmaf(w, a.x, acc.x); acc.y = fmaf(w, a.y, acc.y);
        acc.z = fmaf(w, b.x, acc.z); acc.w = fmaf(w, b.y, acc.w);
    }
    float inv = 1.f / (denom + 1e-16f);
    acc.x *= inv; acc.y *= inv; acc.z *= inv; acc.w *= inv;
    ((float4*)g_agg)[(size_t)node * 32 + lane] = acc;
}

// ---------------- final: out = agg@Wc + x@W2 + b2, fused LN stats ----------------
__global__ void __launch_bounds__(256) k_final(const float* __restrict__ x,
                                               const float* __restrict__ Wc,
                                               float* __restrict__ out, int n) {
    __shared__ float Xs[32][132];
    __shared__ float Ws[32][64];
    __shared__ float rs[8], rss[8];

    int tx = threadIdx.x & 15;
    int ty = threadIdx.x >> 4;
    int row0 = blockIdx.x * 128;

    float acc[8][4];
#pragma unroll
    for (int i = 0; i < 8; i++)
#pragma unroll
        for (int j = 0; j < 4; j++) acc[i][j] = 0.f;

    for (int kc = 0; kc < 6; kc++) {
#pragma unroll
        for (int it = 0; it < 4; it++) {
            int idx = threadIdx.x + it * 256;
            int r = idx >> 3, kq = idx & 7;
            float4 av = make_float4(0.f, 0.f, 0.f, 0.f);
            if (row0 + r < n) {
                if (kc < 4) av = ((const float4*)g_agg)[(size_t)(row0 + r) * 32 + kc * 8 + kq];
                else        av = ((const float4*)x)[(size_t)(row0 + r) * 16 + (kc - 4) * 8 + kq];
            }
            Xs[kq * 4 + 0][r] = av.x;
            Xs[kq * 4 + 1][r] = av.y;
            Xs[kq * 4 + 2][r] = av.z;
            Xs[kq * 4 + 3][r] = av.w;
        }
#pragma unroll
        for (int it = 0; it < 2; it++) {
            int idx = threadIdx.x + it * 256;
            int k = idx >> 4, c4 = idx & 15;
            float4 wv;
            if (kc < 4) wv = ((const float4*)Wc)[(kc * 32 + k) * 16 + c4];
            else        wv = ((const float4*)g_W2)[((kc - 4) * 32 + k) * 16 + c4];
            *(float4*)&Ws[k][c4 * 4] = wv;
        }
        __syncthreads();
#pragma unroll
        for (int k = 0; k < 32; k++) {
            float4 a0 = *(const float4*)&Xs[k][ty * 8];
            float4 a1 = *(const float4*)&Xs[k][ty * 8 + 4];
            float4 b  = *(const float4*)&Ws[k][tx * 4];
            float af[8] = {a0.x, a0.y, a0.z, a0.w, a1.x, a1.y, a1.z, a1.w};
#pragma unroll
            for (int i = 0; i < 8; i++) {
                acc[i][0] = fmaf(af[i], b.x, acc[i][0]);
                acc[i][1] = fmaf(af[i], b.y, acc[i][1]);
                acc[i][2] = fmaf(af[i], b.z, acc[i][2]);
                acc[i][3] = fmaf(af[i], b.w, acc[i][3]);
            }
        }
        __syncthreads();
    }

    float4 b2 = *(const float4*)&g_b2[tx * 4];
    float s = 0.f, ss = 0.f;
#pragma unroll
    for (int i = 0; i < 8; i++) {
        int r = row0 + ty * 8 + i;
        if (r < n) {
            float4 o = make_float4(acc[i][0] + b2.x, acc[i][1] + b2.y,
                                   acc[i][2] + b2.z, acc[i][3] + b2.w);
            *(float4*)&out[(size_t)r * 64 + tx * 4] = o;
            s += (o.x + o.y) + (o.z + o.w);
            ss += o.x * o.x + o.y * o.y + o.z * o.z + o.w * o.w;
        }
    }
#pragma unroll
    for (int off = 16; off > 0; off >>= 1) {
        s  += __shfl_xor_sync(0xffffffffu, s, off);
        ss += __shfl_xor_sync(0xffffffffu, ss, off);
    }
    int wid = threadIdx.x >> 5, lane = threadIdx.x & 31;
    if (lane == 0) { rs[wid] = s; rss[wid] = ss; }
    __syncthreads();
    if (threadIdx.x == 0) {
        double S = 0.0, SS = 0.0;
        for (int w = 0; w < 8; w++) { S += (double)rs[w]; SS += (double)rss[w]; }
        atomicAdd(&g_stats[0], S);
        atomicAdd(&g_stats[1], SS);
    }
}

// ---------------- graph-level LayerNorm ----------------
__global__ void k_norm(float* __restrict__ out, const float* __restrict__ gamma,
                       const float* __restrict__ beta, int total) {
    int i = blockIdx.x * blockDim.x + threadIdx.x;
    if (i < total) {
        double M = (double)total;
        double mean = g_stats[0] / M;
        double var  = g_stats[1] / M - mean * mean;
        if (var < 0.0) var = 0.0;
        float stdv = (float)sqrt(var);
        float v = out[i];
        int d = i & 63;
        out[i] = (v - (float)mean) / (stdv + 1e-5f) * __ldg(&gamma[d]) + __ldg(&beta[d]);
    }
}

// ---------------- launch ----------------
extern "C" void kernel_launch(void* const* d_in, const int* in_sizes, int n_in,
                              void* d_out, int out_size) {
    const float* x    = (const float*)d_in[0];
    const void*  ei   = d_in[1];
    const float* Wq   = (const float*)d_in[2];
    const float* bq   = (const float*)d_in[3];
    const float* Wk   = (const float*)d_in[4];
    const float* Wv   = (const float*)d_in[6];
    const float* bv   = (const float*)d_in[7];
    const float* Wsk  = (const float*)d_in[8];
    const float* bsk  = (const float*)d_in[9];
    const float* Wc   = (const float*)d_in[10];
    const float* bc   = (const float*)d_in[11];
    const float* gam  = (const float*)d_in[12];
    const float* bet  = (const float*)d_in[13];
    float* out = (float*)d_out;

    int n = in_sizes[0] / 64;
    int e = in_sizes[1] / 2;

    k_init<<<(n + 255) / 256, 256>>>(n);
    k_detect<<<1, 32>>>(ei);
    k_convert<<<(2 * e + 255) / 256, 256>>>(ei, e);
    k_prep<<<195, 256>>>(Wq, bq, Wk, Wsk, bsk, Wc, bc);
    k_xb<<<(n * 16 + 255) / 256, 256>>>(x, n);
    k_gemm2<<<dim3((n + 63) / 64, 2), 256>>>(x, Wv, bv, n);
    int nb = (n + 1023) / 1024;
    k_scan1<<<nb, 1024>>>(n);
    k_scan2<<<1, 32>>>(nb, n);
    k_scan3<<<nb, 1024>>>(n);
    k_scatter<<<(e + 255) / 256, 256>>>(e);
    k_attn<<<(n + 7) / 8, 256>>>(n);
    k_final<<<(n + 127) / 128, 256>>>(x, Wc, out, n);
    k_norm<<<(n * 64 + 255) / 256, 256>>>(out, gam, bet, n * 64);
}